// round 16
// baseline (speedup 1.0000x reference)
#include <cuda_runtime.h>
#include <cuda_fp16.h>
#include <math.h>
#include <stdint.h>

// ===================== fixed fast-path dims =====================
#define FN 32768
#define FD 2048
#define FO 2048
#define FE 16

// ===================== GEMM tiling =====================
#define BM 128
#define BN 128
#define BK 64
#define STAGES 3
#define KCHUNKS (FD / BK)          // 32
#define NTH 128                    // 4 warps: 2 (M) x 2 (N), warp tile 64x64

#define ASTRIDE 72                 // 64 + 8 pad elements; 144 bytes/row (16B-aligned)
#define TILE_BYTES (128 * ASTRIDE * 2)         // 18432
#define STAGE_BYTES (2 * TILE_BYTES)           // 36864 (A, B)
#define SMEM_MBAR 0                // full[3] @ 0,8,16; empty[3] @ 24,32,40
#define SMEM_TILE0 1024
#define SMEM_TOTAL (SMEM_TILE0 + STAGES * STAGE_BYTES)   // 111616 -> 2 CTAs/SM

// ===================== scratch (device globals, no allocs) =====================
__device__ __half g_xh[(size_t)FN * FD];
__device__ __half g_wht[(size_t)FE * FO * FD];   // [E][O][D] = B^T, n-major rows

// ===================== asm helpers (base ISA only) =====================
__device__ __forceinline__ void cp_async16(uint32_t saddr, const void* gaddr) {
    asm volatile("cp.async.cg.shared.global [%0], [%1], 16;"
                 :: "r"(saddr), "l"(gaddr));
}
__device__ __forceinline__ uint32_t smem_u32(const void* p) {
    uint32_t a;
    asm("{ .reg .u64 t; cvta.to.shared.u64 t, %1; cvt.u32.u64 %0, t; }" : "=r"(a) : "l"(p));
    return a;
}
__device__ __forceinline__ void ldm_x4(uint32_t addr, uint32_t r[4]) {
    asm volatile("ldmatrix.sync.aligned.m8n8.x4.shared.b16 {%0,%1,%2,%3}, [%4];"
                 : "=r"(r[0]), "=r"(r[1]), "=r"(r[2]), "=r"(r[3])
                 : "r"(addr));
}
// NON-volatile pure register asm: ptxas may interleave HMMAs freely.
__device__ __forceinline__ void mma_16816(float c[4], const uint32_t a[4],
                                          uint32_t b0, uint32_t b1) {
    asm("mma.sync.aligned.m16n8k16.row.col.f32.f16.f16.f32 "
        "{%0,%1,%2,%3}, {%4,%5,%6,%7}, {%8,%9}, {%0,%1,%2,%3};"
        : "+f"(c[0]), "+f"(c[1]), "+f"(c[2]), "+f"(c[3])
        : "r"(a[0]), "r"(a[1]), "r"(a[2]), "r"(a[3]), "r"(b0), "r"(b1));
}

// ---- mbarrier helpers (full fences) ----
__device__ __forceinline__ void mbar_init(uint32_t addr, uint32_t cnt) {
    asm volatile("mbarrier.init.shared.b64 [%0], %1;" :: "r"(addr), "r"(cnt) : "memory");
}
__device__ __forceinline__ void mbar_arrive(uint32_t addr) {
    asm volatile("{ .reg .b64 st; mbarrier.arrive.shared.b64 st, [%0]; }"
                 :: "r"(addr) : "memory");
}
__device__ __forceinline__ void cp_async_mbar_arrive(uint32_t addr) {
    asm volatile("cp.async.mbarrier.arrive.noinc.shared.b64 [%0];"
                 :: "r"(addr) : "memory");
}
__device__ __forceinline__ void mbar_wait_parity(uint32_t addr, uint32_t parity) {
    uint32_t done;
    asm volatile(
        "{\n\t.reg .pred p;\n\t"
        "mbarrier.try_wait.parity.acquire.cta.shared::cta.b64 p, [%1], %2;\n\t"
        "selp.b32 %0, 1, 0, p;\n\t}"
        : "=r"(done) : "r"(addr), "r"(parity) : "memory");
    if (!done) {
        asm volatile(
            "{\n\t.reg .pred P1;\n\t"
            "WL_%=:\n\t"
            "mbarrier.try_wait.parity.acquire.cta.shared::cta.b64 P1, [%0], %1, 0x989680;\n\t"
            "@P1 bra.uni WD_%=;\n\t"
            "bra.uni WL_%=;\n\t"
            "WD_%=:\n\t}" :: "r"(addr), "r"(parity) : "memory");
    }
}

// ===================== fused prep kernel =====================
#define XBLKS 65536   // FN*FD/4 float4 / 256 threads
#define WBLKS 65536   // 16 experts * 64 * 64 tiles of 32x32

__global__ __launch_bounds__(256)
void prep_kernel(const float* __restrict__ x, const float* __restrict__ w,
                 __half* __restrict__ xh, __half* __restrict__ wht) {
    __shared__ float t[32][33];
    const int tid = threadIdx.x;
    if (blockIdx.x < XBLKS) {
        size_t i = (size_t)blockIdx.x * 256 + tid;        // float4 index
        float4 v = reinterpret_cast<const float4*>(x)[i];
        __half2 H01 = __halves2half2(__float2half_rn(v.x), __float2half_rn(v.y));
        __half2 H23 = __halves2half2(__float2half_rn(v.z), __float2half_rn(v.w));
        reinterpret_cast<__half2*>(xh)[2 * i + 0] = H01;
        reinterpret_cast<__half2*>(xh)[2 * i + 1] = H23;
    } else {
        const int bid = blockIdx.x - XBLKS;
        const int e = bid >> 12;                 // /4096
        const int rem = bid & 4095;
        const int k0 = (rem >> 6) * 32;
        const int o0 = (rem & 63) * 32;
        const float* we = w + (size_t)e * FD * FO;
        const int xx = tid & 31, yy = tid >> 5;  // 32 x 8
#pragma unroll
        for (int r = 0; r < 32; r += 8)
            t[yy + r][xx] = we[(size_t)(k0 + yy + r) * FO + o0 + xx];
        __syncthreads();
#pragma unroll
        for (int r = 0; r < 32; r += 8) {
            size_t off = ((size_t)e * FO + o0 + yy + r) * FD + k0 + xx;
            wht[off] = __float2half_rn(t[xx][yy + r]);
        }
    }
}

// ===================== grouped GEMM (mma.sync fp16, mbarrier pipeline,
//   reg double-buffered frags, cp.async issue spread across sub-blocks) ========
__global__ __launch_bounds__(NTH, 2)
void grouped_gemm_mma(const __half* __restrict__ xh,
                      const __half* __restrict__ wht,
                      const int* __restrict__ gsz,
                      float* __restrict__ out) {
    extern __shared__ char sm[];
    const uint32_t sb = smem_u32(sm);

    const int tid = threadIdx.x;
    const int lane = tid & 31;
    const int wid = tid >> 5;      // 0..3
    const int wm = wid & 1;        // 0..1  (M direction, 64 rows)
    const int wn = wid >> 1;       // 0..1  (N direction, 64 cols)
    const int tq = lane >> 2;      // 0..7
    const int colb = (lane & 3) * 2;

    const int m0 = blockIdx.y * BM;
    const int n0 = blockIdx.x * BN;

    // mbarriers
    if (tid == 0) {
#pragma unroll
        for (int s = 0; s < STAGES; ++s) {
            mbar_init(sb + SMEM_MBAR + s * 8, NTH);        // full[s]
            mbar_init(sb + SMEM_MBAR + 24 + s * 8, NTH);   // empty[s]
        }
    }
    __syncthreads();   // one-time: init visible to all threads

    // expert for this M-tile (group sizes are multiples of BM here)
    int e = FE - 1, acc0 = 0;
    for (int i = 0; i < FE; ++i) { acc0 += gsz[i]; if (m0 < acc0) { e = i; break; } }
    const size_t browbase = (size_t)e * FO + n0;

    float acc[4][8][4];
#pragma unroll
    for (int i = 0; i < 4; ++i)
#pragma unroll
        for (int j = 0; j < 8; ++j)
#pragma unroll
            for (int k = 0; k < 4; ++k) acc[i][j][k] = 0.0f;

    // ldmatrix per-lane base offsets (elements) — proven mapping (R6-R15).
    const int q = lane >> 3, r = lane & 7;
    const int a_base = (wm * 64 + (q & 1) * 8 + r) * ASTRIDE + (q >> 1) * 8;
    const int b_base = (wn * 64 + (q >> 1) * 8 + r) * ASTRIDE + (q & 1) * 8;

    // Running global pointers (issue order strictly sequential)
    const int grow = tid >> 3;          // 0..15
    const int gcol = (tid & 7) * 8;     // 0..56
    const __half* gaP = xh  + (size_t)(m0 + grow) * FD + gcol;
    const __half* gbP = wht + (browbase + grow) * FD + gcol;
    const uint32_t soff0 = (uint32_t)(grow * ASTRIDE + gcol) * 2;

    // issue one quarter (2 j-iterations = 4 cp.async) of a stage fill
    auto issue_quarter = [&](int slot, int part) {
        const uint32_t stage = sb + SMEM_TILE0 + (uint32_t)slot * STAGE_BYTES;
#pragma unroll
        for (int j = 0; j < 2; ++j) {
            const int jj = part * 2 + j;
            const uint32_t soff = soff0 + (uint32_t)(jj * 16 * ASTRIDE * 2);
            cp_async16(stage + soff, gaP + (size_t)jj * 16 * FD);
            cp_async16(stage + TILE_BYTES + soff, gbP + (size_t)jj * 16 * FD);
        }
    };
    auto issue_stage = [&](int slot) {
#pragma unroll
        for (int p = 0; p < 4; ++p) issue_quarter(slot, p);
        gaP += BK;
        gbP += BK;
    };

    // double-buffered fragments
    uint32_t ah[2][4][4], bh[2][8][2];

    auto load_frags = [&](uint32_t Ah, uint32_t Bh, int kk, int b) {
#pragma unroll
        for (int i = 0; i < 4; ++i)
            ldm_x4(Ah + (uint32_t)(a_base + i * 16 * ASTRIDE + kk) * 2, ah[b][i]);
#pragma unroll
        for (int jj = 0; jj < 4; ++jj) {
            uint32_t b4[4];
            ldm_x4(Bh + (uint32_t)(b_base + jj * 16 * ASTRIDE + kk) * 2, b4);
            bh[b][2 * jj + 0][0] = b4[0]; bh[b][2 * jj + 0][1] = b4[1];
            bh[b][2 * jj + 1][0] = b4[2]; bh[b][2 * jj + 1][1] = b4[3];
        }
    };

    // prologue: prime stages 0 and 1
#pragma unroll
    for (int s = 0; s < STAGES - 1; ++s) {
        issue_stage(s);
        cp_async_mbar_arrive(sb + SMEM_MBAR + s * 8);
    }

    // peel: wait chunk 0, load its kk=0 fragments into buf 0
    mbar_wait_parity(sb + SMEM_MBAR + 0, 0u);
    load_frags(sb + SMEM_TILE0, sb + SMEM_TILE0 + TILE_BYTES, 0, 0);

    for (int c = 0; c < KCHUNKS; ++c) {
        const int s = c % 3;
        const uint32_t stage = sb + SMEM_TILE0 + (uint32_t)s * STAGE_BYTES;
        const uint32_t Ah = stage;
        const uint32_t Bh = stage + TILE_BYTES;

        const int pc = c + 2;                     // chunk being prefetched
        const int ps = pc % 3;
        const bool do_pf = (pc < KCHUNKS);

#pragma unroll
        for (int kk = 0; kk < BK; kk += 16) {
            const int buf  = (kk >> 4) & 1;
            const int nbuf = buf ^ 1;
            const int part = kk >> 4;             // 0..3

            if (kk < BK - 16) {
                // intra-chunk: next sub-block's fragments into the other buffer
                load_frags(Ah, Bh, kk + 16, nbuf);
                if (kk == BK - 32)      // kk=48 frags issued -> slot reads done
                    mbar_arrive(sb + SMEM_MBAR + 24 + s * 8);
            } else if (c + 1 < KCHUNKS) {
                // cross-chunk: wait next chunk's data, load its kk=0 frags
                const int ns = (c + 1) % 3;
                mbar_wait_parity(sb + SMEM_MBAR + ns * 8,
                                 (uint32_t)(((c + 1) / 3) & 1));
                const uint32_t nstage = sb + SMEM_TILE0 + (uint32_t)ns * STAGE_BYTES;
                load_frags(nstage, nstage + TILE_BYTES, 0, nbuf);
            }

#pragma unroll
            for (int i = 0; i < 4; ++i)
#pragma unroll
                for (int j = 0; j < 8; ++j)
                    mma_16816(acc[i][j], ah[buf][i], bh[buf][j][0], bh[buf][j][1]);

            // prefetch chunk c+2: one quarter per sub-block (smooth LSU load)
            if (do_pf) {
                if (part == 0) {
                    const int k = pc / 3;          // fill index of slot ps
                    if (k >= 1)
                        mbar_wait_parity(sb + SMEM_MBAR + 24 + ps * 8,
                                         (uint32_t)((k - 1) & 1));
                }
                issue_quarter(ps, part);
                if (part == 3) {
                    gaP += BK;
                    gbP += BK;
                    cp_async_mbar_arrive(sb + SMEM_MBAR + ps * 8);
                }
            }
        }
    }

    // epilogue
#pragma unroll
    for (int i = 0; i < 4; ++i) {
        const int row = m0 + wm * 64 + i * 16 + tq;
#pragma unroll
        for (int j = 0; j < 8; ++j) {
            const int ccol = n0 + wn * 64 + j * 8 + colb;
            float2* p0 = reinterpret_cast<float2*>(out + (size_t)row * FO + ccol);
            float2* p1 = reinterpret_cast<float2*>(out + (size_t)(row + 8) * FO + ccol);
            *p0 = make_float2(acc[i][j][0], acc[i][j][1]);
            *p1 = make_float2(acc[i][j][2], acc[i][j][3]);
        }
    }
}

// ===================== fallback SIMT SGEMM (round-1 kernel) =====================
#define FB_BM 128
#define FB_BN 128
#define FB_BK 8
#define FB_TM 8
#define FB_TN 8

__global__ __launch_bounds__(256)
void grouped_sgemm_kernel(const float* __restrict__ x, const float* __restrict__ w,
                          const int* __restrict__ gsz, float* __restrict__ out,
                          int N, int D, int O, int E) {
    __shared__ float As[FB_BK][FB_BM];
    __shared__ float Bs[FB_BK][FB_BN];
    const int m0 = blockIdx.y * FB_BM;
    const int n0 = blockIdx.x * FB_BN;
    if (m0 >= N) return;
    int e = E - 1, acc0 = 0;
    for (int i = 0; i < E; ++i) { acc0 += gsz[i]; if (m0 < acc0) { e = i; break; } }
    const float* wE = w + (size_t)e * D * O;
    const float* xg = x + (size_t)m0 * D;
    const int tid = threadIdx.x;
    const int tx = tid & 15, ty = tid >> 4;
    const int a_row = tid >> 1, a_col = (tid & 1) * 4;
    const int b_row = tid >> 5, b_col = (tid & 31) * 4;
    float accum[FB_TM][FB_TN];
#pragma unroll
    for (int i = 0; i < FB_TM; ++i)
#pragma unroll
        for (int j = 0; j < FB_TN; ++j) accum[i][j] = 0.0f;
    float af[FB_TM], bf[FB_TN];
    for (int k0 = 0; k0 < D; k0 += FB_BK) {
        float4 av = *reinterpret_cast<const float4*>(&xg[(size_t)a_row * D + k0 + a_col]);
        As[a_col + 0][a_row] = av.x; As[a_col + 1][a_row] = av.y;
        As[a_col + 2][a_row] = av.z; As[a_col + 3][a_row] = av.w;
        *reinterpret_cast<float4*>(&Bs[b_row][b_col]) =
            *reinterpret_cast<const float4*>(&wE[(size_t)(k0 + b_row) * O + n0 + b_col]);
        __syncthreads();
#pragma unroll
        for (int k = 0; k < FB_BK; ++k) {
#pragma unroll
            for (int i = 0; i < FB_TM; i += 4) {
                float4 t = *reinterpret_cast<const float4*>(&As[k][ty * FB_TM + i]);
                af[i] = t.x; af[i + 1] = t.y; af[i + 2] = t.z; af[i + 3] = t.w;
            }
#pragma unroll
            for (int j = 0; j < FB_TN; j += 4) {
                float4 t = *reinterpret_cast<const float4*>(&Bs[k][tx * FB_TN + j]);
                bf[j] = t.x; bf[j + 1] = t.y; bf[j + 2] = t.z; bf[j + 3] = t.w;
            }
#pragma unroll
            for (int i = 0; i < FB_TM; ++i)
#pragma unroll
                for (int j = 0; j < FB_TN; ++j)
                    accum[i][j] = fmaf(af[i], bf[j], accum[i][j]);
        }
        __syncthreads();
    }
#pragma unroll
    for (int i = 0; i < FB_TM; ++i) {
        int m = m0 + ty * FB_TM + i;
        if (m >= N) continue;
        float* orow = out + (size_t)m * O + n0 + tx * FB_TN;
#pragma unroll
        for (int j = 0; j < FB_TN; j += 4)
            *reinterpret_cast<float4*>(orow + j) =
                make_float4(accum[i][j], accum[i][j + 1], accum[i][j + 2], accum[i][j + 3]);
    }
}

// ===================== host launch =====================
extern "C" void kernel_launch(void* const* d_in, const int* in_sizes, int n_in,
                              void* d_out, int out_size) {
    const float* x   = (const float*)d_in[0];
    const float* w   = (const float*)d_in[1];
    const int*   gsz = (const int*)d_in[2];
    float*       out = (float*)d_out;

    const long long P = (long long)in_sizes[0];   // N*D
    const long long W = (long long)in_sizes[1];   // E*D*O
    const long long E = (long long)in_sizes[2];
    const long long Q = (long long)out_size;      // N*O
    const long long R = W / E;                    // D*O
    double dD = sqrt((double)P * (double)R / (double)Q);
    int D = (int)(dD + 0.5);
    int N = (int)(P / D);
    int O = (int)(R / D);

    if (N == FN && D == FD && O == FO && (int)E == FE) {
        void *pxh = nullptr, *pwh = nullptr;
        bool ok = true;
        ok &= cudaGetSymbolAddress(&pxh, g_xh)  == cudaSuccess;
        ok &= cudaGetSymbolAddress(&pwh, g_wht) == cudaSuccess;
        ok &= cudaFuncSetAttribute(grouped_gemm_mma,
                                   cudaFuncAttributeMaxDynamicSharedMemorySize,
                                   SMEM_TOTAL) == cudaSuccess;
        if (ok) {
            prep_kernel<<<XBLKS + WBLKS, 256>>>(x, w, (__half*)pxh, (__half*)pwh);
            grouped_gemm_mma<<<dim3(FO / BN, FN / BM), NTH, SMEM_TOTAL>>>(
                (const __half*)pxh, (const __half*)pwh, gsz, out);
            return;
        }
    }

    dim3 block(256);
    dim3 grid((O + FB_BN - 1) / FB_BN, (N + FB_BM - 1) / FB_BM);
    grouped_sgemm_kernel<<<grid, block>>>(x, w, gsz, out, N, D, O, (int)E);
}